// round 3
// baseline (speedup 1.0000x reference)
#include <cuda_runtime.h>
#include <math.h>

// Problem dims
#define BB   16
#define KC   64
#define WW   2048
#define LL   2112      // KC + WW
#define DD   512
#define DHH  256
#define DFFF 2048
#define NLL  4
#define LN_EPS 1e-5f

// ---------------------------------------------------------------------------
// Device scratch (no allocations allowed; statics are the sanctioned path)
// ---------------------------------------------------------------------------
__device__ float g_h  [BB * LL * DD];     // residual stream        (66 MB)
__device__ float g_hn [BB * LL * DD];     // LN output              (66 MB)
__device__ float g_q  [BB * LL * DHH];    // Q                      (33 MB)
__device__ float g_k  [BB * WW * DHH];    // K                      (32 MB)
__device__ float g_v  [BB * WW * DHH];    // V                      (32 MB)
__device__ float g_s  [BB * LL * WW];     // scores / FFN mid       (264 MB; LL*WW == LL*DFFF)
__device__ float g_cat[BB * LL * DD];     // concat(out_a, out_b)   (66 MB)

// ---------------------------------------------------------------------------
// Embedding: h[b][l][d] = item[idx] + pos + segment
// ---------------------------------------------------------------------------
__global__ void embed_kernel(const int* __restrict__ cache, const int* __restrict__ seq,
                             const float* __restrict__ item, const float* __restrict__ cpos,
                             const float* __restrict__ spos, const float* __restrict__ seg,
                             float* __restrict__ h) {
    int r = blockIdx.x;                 // 0 .. BB*LL-1
    int b = r / LL, l = r % LL;
    int idx; const float* pos; const float* sg;
    if (l < KC) { idx = cache[b * KC + l]; pos = cpos + (long)l * DD; sg = seg; }
    else        { int i = l - KC; idx = seq[b * WW + i]; pos = spos + (long)i * DD; sg = seg + DD; }
    const float* it = item + (long)idx * DD;
    float* hr = h + (long)r * DD;
    for (int d = threadIdx.x; d < DD; d += blockDim.x)
        hr[d] = it[d] + pos[d] + sg[d];
}

// ---------------------------------------------------------------------------
// LayerNorm: one block per row of D=512
// ---------------------------------------------------------------------------
__global__ void ln_kernel(const float* __restrict__ x, float* __restrict__ y,
                          const float* __restrict__ g, const float* __restrict__ bia) {
    __shared__ float rs[256], rq[256];
    long row = blockIdx.x;
    const float* xr = x + row * DD;
    float* yr = y + row * DD;
    int t = threadIdx.x;
    float v0 = xr[t], v1 = xr[t + 256];
    float s = v0 + v1, q = v0 * v0 + v1 * v1;
    rs[t] = s; rq[t] = q; __syncthreads();
    for (int o = 128; o > 0; o >>= 1) {
        if (t < o) { rs[t] += rs[t + o]; rq[t] += rq[t + o]; }
        __syncthreads();
    }
    float mean = rs[0] * (1.0f / DD);
    float var  = rq[0] * (1.0f / DD) - mean * mean;
    float inv  = rsqrtf(var + LN_EPS);
    yr[t]       = (v0 - mean) * inv * g[t]       + bia[t];
    yr[t + 256] = (v1 - mean) * inv * g[t + 256] + bia[t + 256];
}

// ---------------------------------------------------------------------------
// Generic batched tiled GEMM. C = alpha*A@B (+bias) (+relu) (+C residual)
// A (M,Kd) row-major lda; B (Kd,N) row-major ldb, or (N,Kd) when TRANSB.
// All M,N multiples of 64; all Kd multiples of 16 -> no bounds checks.
// ---------------------------------------------------------------------------
#define FLAG_RES  1
#define FLAG_RELU 2

template <bool TRANSB>
__global__ __launch_bounds__(256)
void gemm_kernel(const float* __restrict__ A, int lda, long sA,
                 const float* __restrict__ Bm, int ldb, long sB,
                 float* __restrict__ C, int ldc, long sC,
                 int Kd, float alpha, const float* __restrict__ bias, int flags) {
    A  += (long)blockIdx.z * sA;
    Bm += (long)blockIdx.z * sB;
    C  += (long)blockIdx.z * sC;
    const int m0 = blockIdx.y * 64, n0 = blockIdx.x * 64;

    __shared__ float As[16][68];
    __shared__ float Bs[16][68];

    const int tid = threadIdx.x;
    const int tx = tid & 15, ty = tid >> 4;         // output 4x4 micro-tile coords
    const int ar = tid >> 2, ak = (tid & 3) * 4;    // A/transB load coords
    const int bk = tid >> 4, bn = (tid & 15) * 4;   // plain-B load coords

    float acc[4][4] = {{0.f}};

    for (int k0 = 0; k0 < Kd; k0 += 16) {
        float4 av = *(const float4*)&A[(long)(m0 + ar) * lda + k0 + ak];
        As[ak + 0][ar] = av.x; As[ak + 1][ar] = av.y;
        As[ak + 2][ar] = av.z; As[ak + 3][ar] = av.w;
        if (TRANSB) {
            float4 bv = *(const float4*)&Bm[(long)(n0 + ar) * ldb + k0 + ak];
            Bs[ak + 0][ar] = bv.x; Bs[ak + 1][ar] = bv.y;
            Bs[ak + 2][ar] = bv.z; Bs[ak + 3][ar] = bv.w;
        } else {
            float4 bv = *(const float4*)&Bm[(long)(k0 + bk) * ldb + n0 + bn];
            *(float4*)&Bs[bk][bn] = bv;
        }
        __syncthreads();
#pragma unroll
        for (int k = 0; k < 16; k++) {
            float4 a4 = *(const float4*)&As[k][ty * 4];
            float4 b4 = *(const float4*)&Bs[k][tx * 4];
            float a[4] = {a4.x, a4.y, a4.z, a4.w};
            float b[4] = {b4.x, b4.y, b4.z, b4.w};
#pragma unroll
            for (int i = 0; i < 4; i++)
#pragma unroll
                for (int j = 0; j < 4; j++)
                    acc[i][j] = fmaf(a[i], b[j], acc[i][j]);
        }
        __syncthreads();
    }

#pragma unroll
    for (int i = 0; i < 4; i++) {
        long base = (long)(m0 + ty * 4 + i) * ldc + n0 + tx * 4;
#pragma unroll
        for (int j = 0; j < 4; j++) {
            float vv = alpha * acc[i][j];
            if (bias) vv += bias[n0 + tx * 4 + j];
            if (flags & FLAG_RELU) vv = fmaxf(vv, 0.f);
            if (flags & FLAG_RES)  vv += C[base + j];
            C[base + j] = vv;
        }
    }
}

// ---------------------------------------------------------------------------
// Softmax with optional causal mask. One block per (l, b) row; masked tail
// is zeroed so the downstream P@V GEMM can run dense.
// ---------------------------------------------------------------------------
__global__ void softmax_kernel(float* __restrict__ S, int ncols, int causal) {
    __shared__ float red[256];
    int l = blockIdx.x, b = blockIdx.y;
    float* p = S + ((long)b * LL + l) * ncols;
    int valid = causal ? (l < KC ? ncols : (l - KC + 1)) : ncols;
    int t = threadIdx.x;

    float m = -1e30f;
    for (int i = t; i < valid; i += blockDim.x) m = fmaxf(m, p[i]);
    red[t] = m; __syncthreads();
    for (int o = 128; o > 0; o >>= 1) { if (t < o) red[t] = fmaxf(red[t], red[t + o]); __syncthreads(); }
    m = red[0]; __syncthreads();

    float s = 0.f;
    for (int i = t; i < valid; i += blockDim.x) { float e = expf(p[i] - m); p[i] = e; s += e; }
    red[t] = s; __syncthreads();
    for (int o = 128; o > 0; o >>= 1) { if (t < o) red[t] += red[t + o]; __syncthreads(); }
    float inv = 1.0f / red[0];

    for (int i = t; i < ncols; i += blockDim.x)
        p[i] = (i < valid) ? p[i] * inv : 0.f;
}

// ---------------------------------------------------------------------------
// Final LN over the K cache rows + dot with w_ev -> logits
// ---------------------------------------------------------------------------
__global__ void final_kernel(const float* __restrict__ h, const float* __restrict__ fg,
                             const float* __restrict__ fb, const float* __restrict__ wev,
                             const float* __restrict__ bev, float* __restrict__ out) {
    __shared__ float rs[256], rq[256];
    int l = blockIdx.x, b = blockIdx.y;
    const float* xr = h + ((long)b * LL + l) * DD;
    int t = threadIdx.x;
    float v0 = xr[t], v1 = xr[t + 256];
    rs[t] = v0 + v1; rq[t] = v0 * v0 + v1 * v1; __syncthreads();
    for (int o = 128; o > 0; o >>= 1) {
        if (t < o) { rs[t] += rs[t + o]; rq[t] += rq[t + o]; }
        __syncthreads();
    }
    float mean = rs[0] * (1.0f / DD);
    float inv  = rsqrtf(rq[0] * (1.0f / DD) - mean * mean + LN_EPS);
    __syncthreads();
    float d0 = ((v0 - mean) * inv * fg[t]       + fb[t])       * wev[t];
    float d1 = ((v1 - mean) * inv * fg[t + 256] + fb[t + 256]) * wev[t + 256];
    rs[t] = d0 + d1; __syncthreads();
    for (int o = 128; o > 0; o >>= 1) { if (t < o) rs[t] += rs[t + o]; __syncthreads(); }
    if (t == 0) out[b * KC + l] = rs[0] + bev[0];
}

// ---------------------------------------------------------------------------
// Host launcher
// ---------------------------------------------------------------------------
static void gemm(bool transb, const float* A, int lda, long sA,
                 const float* Bm, int ldb, long sB,
                 float* C, int ldc, long sC,
                 int M, int N, int Kd, float alpha,
                 const float* bias, int flags) {
    dim3 grid(N / 64, M / 64, BB);
    if (transb)
        gemm_kernel<true><<<grid, 256>>>(A, lda, sA, Bm, ldb, sB, C, ldc, sC, Kd, alpha, bias, flags);
    else
        gemm_kernel<false><<<grid, 256>>>(A, lda, sA, Bm, ldb, sB, C, ldc, sC, Kd, alpha, bias, flags);
}

extern "C" void kernel_launch(void* const* d_in, const int* in_sizes, int n_in,
                              void* d_out, int out_size) {
    const int*   cache = (const int*)d_in[0];
    const int*   seq   = (const int*)d_in[1];
    const float* item  = (const float*)d_in[2];
    const float* cpos  = (const float*)d_in[3];
    const float* spos  = (const float*)d_in[4];
    const float* seg   = (const float*)d_in[5];
    const float* wq_s  = (const float*)d_in[6];
    const float* wk_s  = (const float*)d_in[7];
    const float* wv_s  = (const float*)d_in[8];
    const float* wq_c  = (const float*)d_in[9];
    const float* wk_c  = (const float*)d_in[10];
    const float* wv_c  = (const float*)d_in[11];
    const float* w_out = (const float*)d_in[12];
    const float* b_out = (const float*)d_in[13];
    const float* ln1g  = (const float*)d_in[14];
    const float* ln1b  = (const float*)d_in[15];
    const float* ln2g  = (const float*)d_in[16];
    const float* ln2b  = (const float*)d_in[17];
    const float* wff1  = (const float*)d_in[18];
    const float* bff1  = (const float*)d_in[19];
    const float* wff2  = (const float*)d_in[20];
    const float* bff2  = (const float*)d_in[21];
    const float* fing  = (const float*)d_in[22];
    const float* finb  = (const float*)d_in[23];
    const float* wev   = (const float*)d_in[24];
    const float* bev   = (const float*)d_in[25];
    float* out = (float*)d_out;

    float *h, *hn, *q, *k, *v, *s, *cat;
    cudaGetSymbolAddress((void**)&h,   g_h);
    cudaGetSymbolAddress((void**)&hn,  g_hn);
    cudaGetSymbolAddress((void**)&q,   g_q);
    cudaGetSymbolAddress((void**)&k,   g_k);
    cudaGetSymbolAddress((void**)&v,   g_v);
    cudaGetSymbolAddress((void**)&s,   g_s);
    cudaGetSymbolAddress((void**)&cat, g_cat);

    const float scale = 0.0625f;   // 1/sqrt(256)
    const long  sHL  = (long)LL * DD;

    embed_kernel<<<BB * LL, 256>>>(cache, seq, item, cpos, spos, seg, h);

    for (int l = 0; l < NLL; l++) {
        const float* Wq_s = wq_s + (long)l * DD * DHH;
        const float* Wk_s = wk_s + (long)l * DD * DHH;
        const float* Wv_s = wv_s + (long)l * DD * DHH;
        const float* Wq_c = wq_c + (long)l * DD * DHH;
        const float* Wk_c = wk_c + (long)l * DD * DHH;
        const float* Wv_c = wv_c + (long)l * DD * DHH;
        const float* Wo   = w_out + (long)l * DD * DD;
        const float* Bo   = b_out + (long)l * DD;
        const float* W1   = wff1 + (long)l * DD * DFFF;
        const float* B1   = bff1 + (long)l * DFFF;
        const float* W2   = wff2 + (long)l * DFFF * DD;
        const float* B2   = bff2 + (long)l * DD;

        // ---- LN1 ----
        ln_kernel<<<BB * LL, 256>>>(h, hn, ln1g + l * DD, ln1b + l * DD);

        // ---- Attention A (seq keys, causal) ----
        gemm(false, hn, DD, sHL, Wq_s, DHH, 0, q, DHH, (long)LL * DHH, LL, DHH, DD, 1.f, nullptr, 0);
        gemm(false, hn + (long)KC * DD, DD, sHL, Wk_s, DHH, 0, k, DHH, (long)WW * DHH, WW, DHH, DD, 1.f, nullptr, 0);
        gemm(false, hn + (long)KC * DD, DD, sHL, Wv_s, DHH, 0, v, DHH, (long)WW * DHH, WW, DHH, DD, 1.f, nullptr, 0);
        gemm(true, q, DHH, (long)LL * DHH, k, DHH, (long)WW * DHH, s, WW, (long)LL * WW, LL, WW, DHH, scale, nullptr, 0);
        softmax_kernel<<<dim3(LL, BB), 256>>>(s, WW, 1);
        gemm(false, s, WW, (long)LL * WW, v, DHH, (long)WW * DHH, cat, DD, sHL, LL, DHH, WW, 1.f, nullptr, 0);

        // ---- Attention B (cache keys, no mask) ----
        gemm(false, hn, DD, sHL, Wq_c, DHH, 0, q, DHH, (long)LL * DHH, LL, DHH, DD, 1.f, nullptr, 0);
        gemm(false, hn, DD, sHL, Wk_c, DHH, 0, k, DHH, (long)KC * DHH, KC, DHH, DD, 1.f, nullptr, 0);
        gemm(false, hn, DD, sHL, Wv_c, DHH, 0, v, DHH, (long)KC * DHH, KC, DHH, DD, 1.f, nullptr, 0);
        gemm(true, q, DHH, (long)LL * DHH, k, DHH, (long)KC * DHH, s, KC, (long)LL * KC, LL, KC, DHH, scale, nullptr, 0);
        softmax_kernel<<<dim3(LL, BB), 256>>>(s, KC, 0);
        gemm(false, s, KC, (long)LL * KC, v, DHH, (long)KC * DHH, cat + DHH, DD, sHL, LL, DHH, KC, 1.f, nullptr, 0);

        // ---- Output projection + residual ----
        gemm(false, cat, DD, sHL, Wo, DD, 0, h, DD, sHL, LL, DD, DD, 1.f, Bo, FLAG_RES);

        // ---- FFN ----
        ln_kernel<<<BB * LL, 256>>>(h, hn, ln2g + l * DD, ln2b + l * DD);
        gemm(false, hn, DD, sHL, W1, DFFF, 0, s, DFFF, (long)LL * DFFF, LL, DFFF, DD, 1.f, B1, FLAG_RELU);
        gemm(false, s, DFFF, (long)LL * DFFF, W2, DD, 0, h, DD, sHL, LL, DD, DFFF, 1.f, B2, FLAG_RES);
    }

    final_kernel<<<dim3(KC, BB), 256>>>(h, fing, finb, wev, bev, out);
}

// round 6
// speedup vs baseline: 2.1373x; 2.1373x over previous
#include <cuda_runtime.h>
#include <cuda_bf16.h>
#include <math.h>

// Problem dims
#define BB   16
#define KC   64
#define WW   2048
#define LL   2112      // KC + WW
#define DD   512
#define DHH  256
#define DFFF 2048
#define NLL  4
#define LN_EPS 1e-5f

// ---------------------------------------------------------------------------
// Device scratch
// ---------------------------------------------------------------------------
__device__ float g_h  [BB * LL * DD];
__device__ float g_hn [BB * LL * DD];
__device__ float g_q  [BB * LL * DHH];
__device__ float g_k  [BB * WW * DHH];
__device__ float g_v  [BB * WW * DHH];
__device__ float g_s  [BB * LL * WW];     // scores / FFN mid
__device__ float g_cat[BB * LL * DD];

// ---------------------------------------------------------------------------
// Embedding
// ---------------------------------------------------------------------------
__global__ void embed_kernel(const int* __restrict__ cache, const int* __restrict__ seq,
                             const float* __restrict__ item, const float* __restrict__ cpos,
                             const float* __restrict__ spos, const float* __restrict__ seg,
                             float* __restrict__ h) {
    int r = blockIdx.x;
    int b = r / LL, l = r % LL;
    int idx; const float* pos; const float* sg;
    if (l < KC) { idx = cache[b * KC + l]; pos = cpos + (long)l * DD; sg = seg; }
    else        { int i = l - KC; idx = seq[b * WW + i]; pos = spos + (long)i * DD; sg = seg + DD; }
    const float* it = item + (long)idx * DD;
    float* hr = h + (long)r * DD;
    for (int d = threadIdx.x; d < DD; d += blockDim.x)
        hr[d] = it[d] + pos[d] + sg[d];
}

// ---------------------------------------------------------------------------
// LayerNorm: grid (rows, BB); row index = blockIdx.y * LL + blockIdx.x
// ---------------------------------------------------------------------------
__global__ void ln_kernel(const float* __restrict__ x, float* __restrict__ y,
                          const float* __restrict__ g, const float* __restrict__ bia) {
    __shared__ float rs[256], rq[256];
    long row = (long)blockIdx.y * LL + blockIdx.x;
    const float* xr = x + row * DD;
    float* yr = y + row * DD;
    int t = threadIdx.x;
    float v0 = xr[t], v1 = xr[t + 256];
    rs[t] = v0 + v1; rq[t] = v0 * v0 + v1 * v1; __syncthreads();
    for (int o = 128; o > 0; o >>= 1) {
        if (t < o) { rs[t] += rs[t + o]; rq[t] += rq[t + o]; }
        __syncthreads();
    }
    float mean = rs[0] * (1.0f / DD);
    float var  = rq[0] * (1.0f / DD) - mean * mean;
    float inv  = rsqrtf(var + LN_EPS);
    yr[t]       = (v0 - mean) * inv * g[t]       + bia[t];
    yr[t + 256] = (v1 - mean) * inv * g[t + 256] + bia[t + 256];
}

// ---------------------------------------------------------------------------
// bf16x3 split tensor-core batched GEMM.
// C = alpha*A@B (+bias) (+relu) (+C residual)
// A (M,Kd) row-major; B (Kd,N) row-major, or (N,Kd) when TRANSB.
// Block tile 128x128x32, 8 warps (2x4), warp tile 64x32, mma m16n8k16 bf16.
// Each fp32 split into bf16 hi+lo; D += Ah*Bh + Ah*Bl + Al*Bh (fp32 accum).
// Kd multiple of 32; M,N arbitrary (clamped loads, predicated stores, N even).
// ---------------------------------------------------------------------------
#define FLAG_RES  1
#define FLAG_RELU 2

__device__ __forceinline__ void split2(float x, float y, unsigned& hi, unsigned& lo) {
    __nv_bfloat16 hx = __float2bfloat16_rn(x);
    __nv_bfloat16 hy = __float2bfloat16_rn(y);
    float rx = x - __bfloat162float(hx);
    float ry = y - __bfloat162float(hy);
    __nv_bfloat16 lx = __float2bfloat16_rn(rx);
    __nv_bfloat16 ly = __float2bfloat16_rn(ry);
    hi = ((unsigned)__bfloat16_as_ushort(hy) << 16) | (unsigned)__bfloat16_as_ushort(hx);
    lo = ((unsigned)__bfloat16_as_ushort(ly) << 16) | (unsigned)__bfloat16_as_ushort(lx);
}

__device__ __forceinline__ void mma_bf16(float* c, const unsigned* a, const unsigned* b) {
    asm volatile(
        "mma.sync.aligned.m16n8k16.row.col.f32.bf16.bf16.f32 "
        "{%0,%1,%2,%3}, {%4,%5,%6,%7}, {%8,%9}, {%0,%1,%2,%3};"
        : "+f"(c[0]), "+f"(c[1]), "+f"(c[2]), "+f"(c[3])
        : "r"(a[0]), "r"(a[1]), "r"(a[2]), "r"(a[3]), "r"(b[0]), "r"(b[1]));
}

template <bool TRANSB>
__global__ __launch_bounds__(256)
void gemm_tc(const float* __restrict__ A, int lda, long sA,
             const float* __restrict__ Bm, int ldb, long sB,
             float* __restrict__ C, int ldc, long sC,
             int M, int N, int Kd, float alpha,
             const float* __restrict__ bias, int flags) {
    // k-pair-major tiles: [pair j = k/2][m or n], pad 136 for conflict-free frags
    __shared__ unsigned Ah[16][136], Al[16][136];
    __shared__ unsigned Bh[16][136], Bl[16][136];

    A  += (long)blockIdx.z * sA;
    Bm += (long)blockIdx.z * sB;
    C  += (long)blockIdx.z * sC;
    const int m0 = blockIdx.y * 128, n0 = blockIdx.x * 128;

    const int tid  = threadIdx.x;
    const int lane = tid & 31;
    const int warp = tid >> 5;
    const int wm = (warp >> 2) * 64;
    const int wn = (warp & 3) * 32;

    float acc[4][4][4] = {{{0.f}}};

    // A load mapping: thread handles 16 consecutive k of one row (4 float4)
    const int am  = tid & 127;
    const int akq = (tid >> 7) * 16;               // 0 or 16
    const float* Aptr = A + (long)min(m0 + am, M - 1) * lda + akq;

    // B load mapping
    const float* Bptr;
    int bn4 = 0, bk = 0;
    if (TRANSB) {
        Bptr = Bm + (long)min(n0 + am, N - 1) * ldb + akq;
    } else {
        bn4 = (tid & 31) * 4;
        bk  = tid >> 5;                            // 0..7 (pair-row base)
        Bptr = Bm + min(n0 + bn4, N - 4);
    }

    const int r = lane >> 2, c = lane & 3;

    for (int k0 = 0; k0 < Kd; k0 += 32) {
        // ---- stage A (split fp32 -> bf16 hi/lo pairs, pair-k-major) ----
#pragma unroll
        for (int i = 0; i < 4; i++) {
            float4 v = *(const float4*)(Aptr + k0 + i * 4);
            int j = (akq >> 1) + i * 2;
            split2(v.x, v.y, Ah[j][am],     Al[j][am]);
            split2(v.z, v.w, Ah[j + 1][am], Al[j + 1][am]);
        }
        // ---- stage B ----
        if (TRANSB) {
#pragma unroll
            for (int i = 0; i < 4; i++) {
                float4 v = *(const float4*)(Bptr + k0 + i * 4);
                int j = (akq >> 1) + i * 2;
                split2(v.x, v.y, Bh[j][am],     Bl[j][am]);
                split2(v.z, v.w, Bh[j + 1][am], Bl[j + 1][am]);
            }
        } else {
#pragma unroll
            for (int i = 0; i < 2; i++) {
                int j = bk + i * 8;                       // pair row
                float4 va = *(const float4*)(Bptr + (long)(k0 + 2 * j)     * ldb);
                float4 vb = *(const float4*)(Bptr + (long)(k0 + 2 * j + 1) * ldb);
                split2(va.x, vb.x, Bh[j][bn4 + 0], Bl[j][bn4 + 0]);
                split2(va.y, vb.y, Bh[j][bn4 + 1], Bl[j][bn4 + 1]);
                split2(va.z, vb.z, Bh[j][bn4 + 2], Bl[j][bn4 + 2]);
                split2(va.w, vb.w, Bh[j][bn4 + 3], Bl[j][bn4 + 3]);
            }
        }
        __syncthreads();

        // ---- compute: 2 mma k-steps of 16 (8 pair-rows each) ----
#pragma unroll
        for (int kkp = 0; kkp < 16; kkp += 8) {
            unsigned ah[4][4], al[4][4], bh[4][2], bl[4][2];
#pragma unroll
            for (int mf = 0; mf < 4; mf++) {
                int m = wm + mf * 16 + r;
                ah[mf][0] = Ah[kkp + c][m];     ah[mf][1] = Ah[kkp + c][m + 8];
                ah[mf][2] = Ah[kkp + 4 + c][m]; ah[mf][3] = Ah[kkp + 4 + c][m + 8];
                al[mf][0] = Al[kkp + c][m];     al[mf][1] = Al[kkp + c][m + 8];
                al[mf][2] = Al[kkp + 4 + c][m]; al[mf][3] = Al[kkp + 4 + c][m + 8];
            }
#pragma unroll
            for (int nf = 0; nf < 4; nf++) {
                int n = wn + nf * 8 + r;
                bh[nf][0] = Bh[kkp + c][n]; bh[nf][1] = Bh[kkp + 4 + c][n];
                bl[nf][0] = Bl[kkp + c][n]; bl[nf][1] = Bl[kkp + 4 + c][n];
            }
#pragma unroll
            for (int mf = 0; mf < 4; mf++)
#pragma unroll
                for (int nf = 0; nf < 4; nf++) {
                    mma_bf16(acc[mf][nf], ah[mf], bh[nf]);
                    mma_bf16(acc[mf][nf], ah[mf], bl[nf]);
                    mma_bf16(acc[mf][nf], al[mf], bh[nf]);
                }
        }
        __syncthreads();
    }

    // ---- epilogue ----
#pragma unroll
    for (int mf = 0; mf < 4; mf++) {
        int r0 = m0 + wm + mf * 16 + r;
#pragma unroll
        for (int nf = 0; nf < 4; nf++) {
            int cc = n0 + wn + nf * 8 + c * 2;
            if (cc < N) {
#pragma unroll
                for (int half = 0; half < 2; half++) {
                    int rr = r0 + half * 8;
                    if (rr < M) {
                        float v0 = alpha * acc[mf][nf][half * 2 + 0];
                        float v1 = alpha * acc[mf][nf][half * 2 + 1];
                        if (bias) { v0 += bias[cc]; v1 += bias[cc + 1]; }
                        if (flags & FLAG_RELU) { v0 = fmaxf(v0, 0.f); v1 = fmaxf(v1, 0.f); }
                        long base = (long)rr * ldc + cc;
                        if (flags & FLAG_RES) { v0 += C[base]; v1 += C[base + 1]; }
                        C[base] = v0; C[base + 1] = v1;
                    }
                }
            }
        }
    }
}

// ---------------------------------------------------------------------------
// Softmax; grid (rows, BB); masked tail zeroed -> dense PV GEMM
// ---------------------------------------------------------------------------
__global__ void softmax_kernel(float* __restrict__ S, int ncols, int rows, int causal) {
    __shared__ float red[256];
    int l = blockIdx.x, b = blockIdx.y;
    float* p = S + ((long)b * rows + l) * ncols;
    int valid = causal ? (l < KC ? ncols : (l - KC + 1)) : ncols;
    int t = threadIdx.x;

    float m = -1e30f;
    for (int i = t; i < valid; i += blockDim.x) m = fmaxf(m, p[i]);
    red[t] = m; __syncthreads();
    for (int o = 128; o > 0; o >>= 1) { if (t < o) red[t] = fmaxf(red[t], red[t + o]); __syncthreads(); }
    m = red[0]; __syncthreads();

    float s = 0.f;
    for (int i = t; i < valid; i += blockDim.x) { float e = expf(p[i] - m); p[i] = e; s += e; }
    red[t] = s; __syncthreads();
    for (int o = 128; o > 0; o >>= 1) { if (t < o) red[t] += red[t + o]; __syncthreads(); }
    float inv = 1.0f / red[0];

    for (int i = t; i < ncols; i += blockDim.x)
        p[i] = (i < valid) ? p[i] * inv : 0.f;
}

// ---------------------------------------------------------------------------
// Final LN over the K cache rows + dot with w_ev -> logits
// ---------------------------------------------------------------------------
__global__ void final_kernel(const float* __restrict__ h, const float* __restrict__ fg,
                             const float* __restrict__ fb, const float* __restrict__ wev,
                             const float* __restrict__ bev, float* __restrict__ out) {
    __shared__ float rs[256], rq[256];
    int l = blockIdx.x, b = blockIdx.y;
    const float* xr = h + ((long)b * LL + l) * DD;
    int t = threadIdx.x;
    float v0 = xr[t], v1 = xr[t + 256];
    rs[t] = v0 + v1; rq[t] = v0 * v0 + v1 * v1; __syncthreads();
    for (int o = 128; o > 0; o >>= 1) {
        if (t < o) { rs[t] += rs[t + o]; rq[t] += rq[t + o]; }
        __syncthreads();
    }
    float mean = rs[0] * (1.0f / DD);
    float inv  = rsqrtf(rq[0] * (1.0f / DD) - mean * mean + LN_EPS);
    __syncthreads();
    float d0 = ((v0 - mean) * inv * fg[t]       + fb[t])       * wev[t];
    float d1 = ((v1 - mean) * inv * fg[t + 256] + fb[t + 256]) * wev[t + 256];
    rs[t] = d0 + d1; __syncthreads();
    for (int o = 128; o > 0; o >>= 1) { if (t < o) rs[t] += rs[t + o]; __syncthreads(); }
    if (t == 0) out[b * KC + l] = rs[0] + bev[0];
}

// ---------------------------------------------------------------------------
// Host launcher
// ---------------------------------------------------------------------------
static void gemm(bool transb, const float* A, int lda, long sA,
                 const float* Bm, int ldb, long sB,
                 float* C, int ldc, long sC,
                 int M, int N, int Kd, float alpha,
                 const float* bias, int flags) {
    dim3 grid((N + 127) / 128, (M + 127) / 128, BB);
    if (transb)
        gemm_tc<true><<<grid, 256>>>(A, lda, sA, Bm, ldb, sB, C, ldc, sC, M, N, Kd, alpha, bias, flags);
    else
        gemm_tc<false><<<grid, 256>>>(A, lda, sA, Bm, ldb, sB, C, ldc, sC, M, N, Kd, alpha, bias, flags);
}

extern "C" void kernel_launch(void* const* d_in, const int* in_sizes, int n_in,
                              void* d_out, int out_size) {
    const int*   cache = (const int*)d_in[0];
    const int*   seq   = (const int*)d_in[1];
    const float* item  = (const float*)d_in[2];
    const float* cpos  = (const float*)d_in[3];
    const float* spos  = (const float*)d_in[4];
    const float* seg   = (const float*)d_in[5];
    const float* wq_s  = (const float*)d_in[6];
    const float* wk_s  = (const float*)d_in[7];
    const float* wv_s  = (const float*)d_in[8];
    const float* wq_c  = (const float*)d_in[9];
    const float* wk_c  = (const float*)d_in[10];
    const float* wv_c  = (const float*)d_in[11];
    const float* w_out = (const float*)d_in[12];
    const float* b_out = (const float*)d_in[13];
    const float* ln1g  = (const float*)d_in[14];
    const float* ln1b  = (const float*)d_in[15];
    const float* ln2g  = (const float*)d_in[16];
    const float* ln2b  = (const float*)d_in[17];
    const float* wff1  = (const float*)d_in[18];
    const float* bff1  = (const float*)d_in[19];
    const float* wff2  = (const float*)d_in[20];
    const float* bff2  = (const float*)d_in[21];
    const float* fing  = (const float*)d_in[22];
    const float* finb  = (const float*)d_in[23];
    const float* wev   = (const float*)d_in[24];
    const float* bev   = (const float*)d_in[25];
    float* out = (float*)d_out;

    float *h, *hn, *q, *k, *v, *s, *cat;
    cudaGetSymbolAddress((void**)&h,   g_h);
    cudaGetSymbolAddress((void**)&hn,  g_hn);
    cudaGetSymbolAddress((void**)&q,   g_q);
    cudaGetSymbolAddress((void**)&k,   g_k);
    cudaGetSymbolAddress((void**)&v,   g_v);
    cudaGetSymbolAddress((void**)&s,   g_s);
    cudaGetSymbolAddress((void**)&cat, g_cat);

    const float scale = 0.0625f;   // 1/sqrt(256)
    const long  sHL  = (long)LL * DD;

    embed_kernel<<<BB * LL, 256>>>(cache, seq, item, cpos, spos, seg, h);

    for (int l = 0; l < NLL; l++) {
        const float* Wq_s = wq_s + (long)l * DD * DHH;
        const float* Wk_s = wk_s + (long)l * DD * DHH;
        const float* Wv_s = wv_s + (long)l * DD * DHH;
        const float* Wq_c = wq_c + (long)l * DD * DHH;
        const float* Wk_c = wk_c + (long)l * DD * DHH;
        const float* Wv_c = wv_c + (long)l * DD * DHH;
        const float* Wo   = w_out + (long)l * DD * DD;
        const float* Bo   = b_out + (long)l * DD;
        const float* W1   = wff1 + (long)l * DD * DFFF;
        const float* B1   = bff1 + (long)l * DFFF;
        const float* W2   = wff2 + (long)l * DFFF * DD;
        const float* B2   = bff2 + (long)l * DD;

        // Last layer: only the K=64 cache rows feed the output head.
        const int Mq = (l == NLL - 1) ? KC : LL;
        const long sQ = (long)Mq * DHH;

        // ---- LN1 (full: K/V need every row) ----
        ln_kernel<<<dim3(LL, BB), 256>>>(h, hn, ln1g + l * DD, ln1b + l * DD);

        // ---- Attention A (seq keys, causal) ----
        gemm(false, hn, DD, sHL, Wq_s, DHH, 0, q, DHH, sQ, Mq, DHH, DD, 1.f, nullptr, 0);
        gemm(false, hn + (long)KC * DD, DD, sHL, Wk_s, DHH, 0, k, DHH, (long)WW * DHH, WW, DHH, DD, 1.f, nullptr, 0);
        gemm(false, hn + (long)KC * DD, DD, sHL, Wv_s, DHH, 0, v, DHH, (long)WW * DHH, WW, DHH, DD, 1.f, nullptr, 0);
        gemm(true, q, DHH, sQ, k, DHH, (long)WW * DHH, s, WW, (long)Mq * WW, Mq, WW, DHH, scale, nullptr, 0);
        softmax_kernel<<<dim3(Mq, BB), 256>>>(s, WW, Mq, 1);
        gemm(false, s, WW, (long)Mq * WW, v, DHH, (long)WW * DHH, cat, DD, sHL, Mq, DHH, WW, 1.f, nullptr, 0);

        // ---- Attention B (cache keys, no mask) ----
        gemm(false, hn, DD, sHL, Wq_c, DHH, 0, q, DHH, sQ, Mq, DHH, DD, 1.f, nullptr, 0);
        gemm(false, hn, DD, sHL, Wk_c, DHH, 0, k, DHH, (long)KC * DHH, KC, DHH, DD, 1.f, nullptr, 0);
        gemm(false, hn, DD, sHL, Wv_c, DHH, 0, v, DHH, (long)KC * DHH, KC, DHH, DD, 1.f, nullptr, 0);
        gemm(true, q, DHH, sQ, k, DHH, (long)KC * DHH, s, KC, (long)Mq * KC, Mq, KC, DHH, scale, nullptr, 0);
        softmax_kernel<<<dim3(Mq, BB), 256>>>(s, KC, Mq, 0);
        gemm(false, s, KC, (long)Mq * KC, v, DHH, (long)KC * DHH, cat + DHH, DD, sHL, Mq, DHH, KC, 1.f, nullptr, 0);

        // ---- Output projection + residual ----
        gemm(false, cat, DD, sHL, Wo, DD, 0, h, DD, sHL, Mq, DD, DD, 1.f, Bo, FLAG_RES);

        // ---- FFN ----
        ln_kernel<<<dim3(Mq, BB), 256>>>(h, hn, ln2g + l * DD, ln2b + l * DD);
        gemm(false, hn, DD, sHL, W1, DFFF, 0, s, DFFF, (long)Mq * DFFF, Mq, DFFF, DD, 1.f, B1, FLAG_RELU);
        gemm(false, s, DFFF, (long)Mq * DFFF, W2, DD, 0, h, DD, sHL, Mq, DD, DFFF, 1.f, B2, FLAG_RES);
    }

    final_kernel<<<dim3(KC, BB), 256>>>(h, fing, finb, wev, bev, out);
}